// round 12
// baseline (speedup 1.0000x reference)
#include <cuda_runtime.h>
#include <cstdint>

#define BB 16384
#define TT 2048

// Scratch: x transposed to [T, B]; padded by one timestep so the prefetch of
// t+1 never branches (last prefetched value is read but never used).
__device__ float g_xT[(size_t)BB * (size_t)(TT + 1)];

typedef unsigned long long ull;

__device__ __forceinline__ ull pk2(float a, float b) {
    ull r; asm("mov.b64 %0, {%1, %2};" : "=l"(r) : "f"(a), "f"(b)); return r;
}
__device__ __forceinline__ void upk2(ull v, float& a, float& b) {
    asm("mov.b64 {%0, %1}, %2;" : "=f"(a), "=f"(b) : "l"(v));
}
__device__ __forceinline__ ull ffma2(ull a, ull b, ull c) {
    ull d; asm("fma.rn.f32x2 %0, %1, %2, %3;" : "=l"(d) : "l"(a), "l"(b), "l"(c)); return d;
}
__device__ __forceinline__ ull fsub2(ull a, ull b) {
    ull d; asm("sub.rn.f32x2 %0, %1, %2;" : "=l"(d) : "l"(a), "l"(b)); return d;
}
// MUFU.TANH — single-instruction tanh (sm_75+)
__device__ __forceinline__ float tanh_mufu(float x) {
    float y; asm("tanh.approx.f32 %0, %1;" : "=f"(y) : "f"(x)); return y;
}
__device__ __forceinline__ float hadd2(ull v) {
    float a, b; upk2(v, a, b); return a + b;
}

// ---------------------------------------------------------------------------
// Kernel 1: transpose x [B, T] -> g_xT [T, B]
// ---------------------------------------------------------------------------
__global__ void transpose_kernel(const float* __restrict__ x) {
    __shared__ float tile[32][33];
    int t0 = blockIdx.x * 32;
    int b0 = blockIdx.y * 32;
    int tx = threadIdx.x, ty = threadIdx.y;
#pragma unroll
    for (int i = 0; i < 4; i++) {
        tile[ty + i * 8][tx] = x[(size_t)(b0 + ty + i * 8) * TT + (t0 + tx)];
    }
    __syncthreads();
#pragma unroll
    for (int i = 0; i < 4; i++) {
        g_xT[(size_t)(t0 + ty + i * 8) * BB + (b0 + tx)] = tile[tx][ty + i * 8];
    }
}

// ---------------------------------------------------------------------------
// Kernel 2: GRU scan — SINGLE WAVE. k-packed weights (48 regs), 4 elements
//           per thread (2 packed pairs), packed f32x2 tails.
//   - Lane j (= tid&15) owns hidden index j, gate rows {j,16+j,32+j}.
//   - 16-lane group = 4 batch elements; per step: dot(pair0), dot(pair1)
//     [12 independent 8-deep ffma2 chains], then two independent packed
//     tails that overlap each other and other warps' dots.
//   - SMEM exchange: group region 80 floats, elem slots at +0,+20,+40,+60
//     (bank offsets 0/20/8/28 mod 32; two groups per warp 16 banks apart)
//     -> conflict-free STS.32 writes and broadcast LDS.128 reads.
//   - 1024 blocks x 64 thr, __launch_bounds__(64,7): 7 blocks/SM -> 1036
//     slots >= 1024 blocks -> ONE WAVE.
//   - r/z recurrent weights+biases pre-scaled by 0.5 (sigmoid via tanh).
// ---------------------------------------------------------------------------

#define GREG 80   // floats per group region
#define E1OFF 20
#define E2OFF 40
#define E3OFF 60

__global__ __launch_bounds__(64, 7)
void gru_kernel(const float* __restrict__ w_ih, const float* __restrict__ w_hh,
                const float* __restrict__ b_ih, const float* __restrict__ b_hh,
                const float* __restrict__ w_fc, const float* __restrict__ b_fc,
                float* __restrict__ out)
{
    __shared__ float hbuf[2][4 * GREG];

    int tid = threadIdx.x;
    int j   = tid & 15;                       // owned hidden index
    int grp = tid >> 4;                       // group within block (0..3)
    int gid = (blockIdx.x * 64 + tid) >> 4;   // global group; elements 4gid..4gid+3

    // --- k-packed register weights: 8 ull per gate row, 24 ull total ---
    ull wr2[8], wz2[8], wn2[8];
#pragma unroll
    for (int m = 0; m < 8; m++) {
        wr2[m] = pk2(0.5f * __ldg(&w_hh[j * 16 + 2 * m]),
                     0.5f * __ldg(&w_hh[j * 16 + 2 * m + 1]));
        wz2[m] = pk2(0.5f * __ldg(&w_hh[(16 + j) * 16 + 2 * m]),
                     0.5f * __ldg(&w_hh[(16 + j) * 16 + 2 * m + 1]));
        wn2[m] = pk2(__ldg(&w_hh[(32 + j) * 16 + 2 * m]),
                     __ldg(&w_hh[(32 + j) * 16 + 2 * m + 1]));
    }

    // --- tail constants ---
    float wirf = 0.5f * __ldg(&w_ih[j]);
    float wizf = 0.5f * __ldg(&w_ih[16 + j]);
    float winf = __ldg(&w_ih[32 + j]);
    float bsrf = 0.5f * (__ldg(&b_ih[j]) + __ldg(&b_hh[j]));
    float bszf = 0.5f * (__ldg(&b_ih[16 + j]) + __ldg(&b_hh[16 + j]));
    float binf = __ldg(&b_ih[32 + j]);
    float bhnf = __ldg(&b_hh[32 + j]);
    ull bR2 = pk2(bsrf, 0.0f);     // dot-chain init addends (bias in lo half)
    ull bZ2 = pk2(bszf, 0.0f);
    ull bN2 = pk2(bhnf, 0.0f);
    ull wirp  = pk2(wirf, wirf);   // packed duplicated tail constants
    ull wizp  = pk2(wizf, wizf);
    ull winp  = pk2(winf, winf);
    ull binp2 = pk2(binf, binf);
    ull halfp = pk2(0.5f, 0.5f);

    // ping-pong pointers (static offsets, swapped each step)
    float* rd0 = &hbuf[0][grp * GREG];
    float* wr0 = &hbuf[1][grp * GREG];

    ull h01 = 0ull, h23 = 0ull;    // packed h for (e0,e1), (e2,e3)
    rd0[j]         = 0.0f;
    rd0[j + E1OFF] = 0.0f;
    rd0[j + E2OFF] = 0.0f;
    rd0[j + E3OFF] = 0.0f;
    __syncwarp();

    const float4* xp = ((const float4*)g_xT) + gid;
    float4 xv = __ldg(xp);
    xp += (BB / 4);

    for (int t = 0; t < TT; t++) {
        ull x01 = pk2(xv.x, xv.y);
        ull x23 = pk2(xv.z, xv.w);
        float4 xnext = __ldg(xp);      // padded array: always valid
        xp += (BB / 4);

        // ================= dot pair 0 (elements 0,1) =================
        ull aR0, aZ0, aN0, aR1, aZ1, aN1;
        {
            ulonglong2 v0 = *(const ulonglong2*)(rd0);
            ulonglong2 v1 = *(const ulonglong2*)(rd0 + E1OFF);
            aR0 = ffma2(wr2[0], v0.x, bR2);  aR1 = ffma2(wr2[0], v1.x, bR2);
            aZ0 = ffma2(wz2[0], v0.x, bZ2);  aZ1 = ffma2(wz2[0], v1.x, bZ2);
            aN0 = ffma2(wn2[0], v0.x, bN2);  aN1 = ffma2(wn2[0], v1.x, bN2);
            aR0 = ffma2(wr2[1], v0.y, aR0);  aR1 = ffma2(wr2[1], v1.y, aR1);
            aZ0 = ffma2(wz2[1], v0.y, aZ0);  aZ1 = ffma2(wz2[1], v1.y, aZ1);
            aN0 = ffma2(wn2[1], v0.y, aN0);  aN1 = ffma2(wn2[1], v1.y, aN1);
#pragma unroll
            for (int c = 1; c < 4; c++) {
                ulonglong2 u0 = *(const ulonglong2*)(rd0 + 4 * c);
                ulonglong2 u1 = *(const ulonglong2*)(rd0 + E1OFF + 4 * c);
                aR0 = ffma2(wr2[2 * c], u0.x, aR0);      aR1 = ffma2(wr2[2 * c], u1.x, aR1);
                aZ0 = ffma2(wz2[2 * c], u0.x, aZ0);      aZ1 = ffma2(wz2[2 * c], u1.x, aZ1);
                aN0 = ffma2(wn2[2 * c], u0.x, aN0);      aN1 = ffma2(wn2[2 * c], u1.x, aN1);
                aR0 = ffma2(wr2[2 * c + 1], u0.y, aR0);  aR1 = ffma2(wr2[2 * c + 1], u1.y, aR1);
                aZ0 = ffma2(wz2[2 * c + 1], u0.y, aZ0);  aZ1 = ffma2(wz2[2 * c + 1], u1.y, aZ1);
                aN0 = ffma2(wn2[2 * c + 1], u0.y, aN0);  aN1 = ffma2(wn2[2 * c + 1], u1.y, aN1);
            }
        }

        // ================= dot pair 1 (elements 2,3) =================
        ull aR2, aZ2, aN2, aR3, aZ3, aN3;
        {
            ulonglong2 v2 = *(const ulonglong2*)(rd0 + E2OFF);
            ulonglong2 v3 = *(const ulonglong2*)(rd0 + E3OFF);
            aR2 = ffma2(wr2[0], v2.x, bR2);  aR3 = ffma2(wr2[0], v3.x, bR2);
            aZ2 = ffma2(wz2[0], v2.x, bZ2);  aZ3 = ffma2(wz2[0], v3.x, bZ2);
            aN2 = ffma2(wn2[0], v2.x, bN2);  aN3 = ffma2(wn2[0], v3.x, bN2);
            aR2 = ffma2(wr2[1], v2.y, aR2);  aR3 = ffma2(wr2[1], v3.y, aR3);
            aZ2 = ffma2(wz2[1], v2.y, aZ2);  aZ3 = ffma2(wz2[1], v3.y, aZ3);
            aN2 = ffma2(wn2[1], v2.y, aN2);  aN3 = ffma2(wn2[1], v3.y, aN3);
#pragma unroll
            for (int c = 1; c < 4; c++) {
                ulonglong2 u2 = *(const ulonglong2*)(rd0 + E2OFF + 4 * c);
                ulonglong2 u3 = *(const ulonglong2*)(rd0 + E3OFF + 4 * c);
                aR2 = ffma2(wr2[2 * c], u2.x, aR2);      aR3 = ffma2(wr2[2 * c], u3.x, aR3);
                aZ2 = ffma2(wz2[2 * c], u2.x, aZ2);      aZ3 = ffma2(wz2[2 * c], u3.x, aZ3);
                aN2 = ffma2(wn2[2 * c], u2.x, aN2);      aN3 = ffma2(wn2[2 * c], u3.x, aN3);
                aR2 = ffma2(wr2[2 * c + 1], u2.y, aR2);  aR3 = ffma2(wr2[2 * c + 1], u3.y, aR3);
                aZ2 = ffma2(wz2[2 * c + 1], u2.y, aZ2);  aZ3 = ffma2(wz2[2 * c + 1], u3.y, aZ3);
                aN2 = ffma2(wn2[2 * c + 1], u2.y, aN2);  aN3 = ffma2(wn2[2 * c + 1], u3.y, aN3);
            }
        }

        // ================= packed tail pair 0 =================
        {
            ull sR = pk2(hadd2(aR0), hadd2(aR1));
            ull sZ = pk2(hadd2(aZ0), hadd2(aZ1));
            ull gN = pk2(hadd2(aN0), hadd2(aN1));
            sR = ffma2(x01, wirp, sR);
            sZ = ffma2(x01, wizp, sZ);
            ull gI = ffma2(x01, winp, binp2);
            float lo, hi;
            upk2(sR, lo, hi);
            ull rr = ffma2(halfp, pk2(tanh_mufu(lo), tanh_mufu(hi)), halfp);
            upk2(sZ, lo, hi);
            ull zz = ffma2(halfp, pk2(tanh_mufu(lo), tanh_mufu(hi)), halfp);
            ull npre = ffma2(rr, gN, gI);
            upk2(npre, lo, hi);
            ull nn = pk2(tanh_mufu(lo), tanh_mufu(hi));
            h01 = ffma2(zz, fsub2(h01, nn), nn);
        }
        // ================= packed tail pair 1 =================
        {
            ull sR = pk2(hadd2(aR2), hadd2(aR3));
            ull sZ = pk2(hadd2(aZ2), hadd2(aZ3));
            ull gN = pk2(hadd2(aN2), hadd2(aN3));
            sR = ffma2(x23, wirp, sR);
            sZ = ffma2(x23, wizp, sZ);
            ull gI = ffma2(x23, winp, binp2);
            float lo, hi;
            upk2(sR, lo, hi);
            ull rr = ffma2(halfp, pk2(tanh_mufu(lo), tanh_mufu(hi)), halfp);
            upk2(sZ, lo, hi);
            ull zz = ffma2(halfp, pk2(tanh_mufu(lo), tanh_mufu(hi)), halfp);
            ull npre = ffma2(rr, gN, gI);
            upk2(npre, lo, hi);
            ull nn = pk2(tanh_mufu(lo), tanh_mufu(hi));
            h23 = ffma2(zz, fsub2(h23, nn), nn);
        }

        // ================= exchange =================
        float hv0, hv1, hv2, hv3;
        upk2(h01, hv0, hv1);
        upk2(h23, hv2, hv3);
        wr0[j]         = hv0;
        wr0[j + E1OFF] = hv1;
        wr0[j + E2OFF] = hv2;
        wr0[j + E3OFF] = hv3;
        __syncwarp();
        float* tp = rd0; rd0 = wr0; wr0 = tp;

        xv = xnext;
    }

    // FC epilogue: out[b] = sum_j h[b][j] * w_fc[j] + b_fc
    float wf = __ldg(&w_fc[j]);
    float hv0, hv1, hv2, hv3;
    upk2(h01, hv0, hv1);
    upk2(h23, hv2, hv3);
    float s0 = hv0 * wf, s1 = hv1 * wf, s2 = hv2 * wf, s3 = hv3 * wf;
#pragma unroll
    for (int d = 1; d < 16; d <<= 1) {
        s0 += __shfl_xor_sync(0xffffffffu, s0, d);
        s1 += __shfl_xor_sync(0xffffffffu, s1, d);
        s2 += __shfl_xor_sync(0xffffffffu, s2, d);
        s3 += __shfl_xor_sync(0xffffffffu, s3, d);
    }
    if (j == 0) {
        float bf = __ldg(b_fc);
        float4 o;
        o.x = s0 + bf; o.y = s1 + bf; o.z = s2 + bf; o.w = s3 + bf;
        *(float4*)(out + 4 * gid) = o;
    }
}

// ---------------------------------------------------------------------------
extern "C" void kernel_launch(void* const* d_in, const int* in_sizes, int n_in,
                              void* d_out, int out_size)
{
    const float* x    = (const float*)d_in[0];
    const float* w_ih = (const float*)d_in[1];
    const float* w_hh = (const float*)d_in[2];
    const float* b_ih = (const float*)d_in[3];
    const float* b_hh = (const float*)d_in[4];
    const float* w_fc = (const float*)d_in[5];
    const float* b_fc = (const float*)d_in[6];
    float* out = (float*)d_out;

    dim3 tb(32, 8);
    dim3 tg(TT / 32, BB / 32);
    transpose_kernel<<<tg, tb>>>(x);

    // 16384 elems / 4 per 16-lane group * 16 lanes = 65536 threads
    // = 1024 blocks x 64 threads; 7 blocks/SM -> 1036 slots -> ONE WAVE.
    gru_kernel<<<1024, 64>>>(w_ih, w_hh, b_ih, b_hh, w_fc, b_fc, out);
}

// round 13
// speedup vs baseline: 1.0331x; 1.0331x over previous
#include <cuda_runtime.h>
#include <cstdint>

#define BB 16384
#define TT 2048

// Scratch: x transposed to [T, B]; padded by one timestep so the prefetch of
// t+1 never branches (last prefetched value is read but never used).
__device__ float g_xT[(size_t)BB * (size_t)(TT + 1)];

typedef unsigned long long ull;

__device__ __forceinline__ ull pk2(float a, float b) {
    ull r; asm("mov.b64 %0, {%1, %2};" : "=l"(r) : "f"(a), "f"(b)); return r;
}
__device__ __forceinline__ void upk2(ull v, float& a, float& b) {
    asm("mov.b64 {%0, %1}, %2;" : "=f"(a), "=f"(b) : "l"(v));
}
__device__ __forceinline__ ull ffma2(ull a, ull b, ull c) {
    ull d; asm("fma.rn.f32x2 %0, %1, %2, %3;" : "=l"(d) : "l"(a), "l"(b), "l"(c)); return d;
}
__device__ __forceinline__ ull fsub2(ull a, ull b) {
    ull d; asm("sub.rn.f32x2 %0, %1, %2;" : "=l"(d) : "l"(a), "l"(b)); return d;
}
// MUFU.TANH — single-instruction tanh (sm_75+)
__device__ __forceinline__ float tanh_mufu(float x) {
    float y; asm("tanh.approx.f32 %0, %1;" : "=f"(y) : "f"(x)); return y;
}

// ---------------------------------------------------------------------------
// Kernel 1: transpose x [B, T] -> g_xT [T, B]
// ---------------------------------------------------------------------------
__global__ void transpose_kernel(const float* __restrict__ x) {
    __shared__ float tile[32][33];
    int t0 = blockIdx.x * 32;
    int b0 = blockIdx.y * 32;
    int tx = threadIdx.x, ty = threadIdx.y;
#pragma unroll
    for (int i = 0; i < 4; i++) {
        tile[ty + i * 8][tx] = x[(size_t)(b0 + ty + i * 8) * TT + (t0 + tx)];
    }
    __syncthreads();
#pragma unroll
    for (int i = 0; i < 4; i++) {
        g_xT[(size_t)(t0 + ty + i * 8) * BB + (b0 + tx)] = tile[tx][ty + i * 8];
    }
}

// ---------------------------------------------------------------------------
// Kernel 2: GRU scan — GATE-PACKED r/z chains + batch-packed n chain.
//   - 16-lane group = one batch pair. Lane j owns hidden index j.
//   - Chains per step (each 16 ffma2 deep, 3-way ILP like round 6):
//       A1 = (aR0, aZ0) : weights (wr_k, wz_k), operand (h0_k, h0_k)
//       A2 = (aR1, aZ1) : same weights,        operand (h1_k, h1_k)
//       AN = (aN0, aN1) : weights (wn_k, wn_k), operand (h0_k, h1_k)
//     -> weight registers 64 (vs 96 duplicated in round 6) => NO SPILLS,
//        and no horizontal adds (pre-activations come out complete).
//   - h exchange: 3 SMEM layouts per group (dup0, dup1, mix), 3x STS.64
//     per step; dot reads are broadcast LDS.128 (2 addresses per warp).
//     Group stride 52 ull staggers banks.
//   - __launch_bounds__(128,4): cap 128 regs (est. need ~118), 16 warps/SM,
//     identical occupancy shape to round 6 but spill-free.
//   - r/z weights+biases pre-scaled by 0.5 (sigmoid via tanh identity).
// ---------------------------------------------------------------------------

#define GSTRIDE 52   // ull per group region (48 + 4 pad)

__global__ __launch_bounds__(128, 4)
void gru_kernel(const float* __restrict__ w_ih, const float* __restrict__ w_hh,
                const float* __restrict__ b_ih, const float* __restrict__ b_hh,
                const float* __restrict__ w_fc, const float* __restrict__ b_fc,
                float* __restrict__ out)
{
    __shared__ ull hbuf[2][8 * GSTRIDE];

    int tid = threadIdx.x;
    int g   = blockIdx.x * 128 + tid;
    int j   = g & 15;          // owned hidden index
    int p   = g >> 4;          // global batch-pair index (elements 2p, 2p+1)
    int grp = tid >> 4;        // group within block (0..7)

    // --- register weights: 32 ull = 64 regs total ---
    ull wrz_[16], wn_[16];
#pragma unroll
    for (int k = 0; k < 16; k++) {
        float wr = 0.5f * __ldg(&w_hh[j * 16 + k]);          // r row, half-scaled
        float wz = 0.5f * __ldg(&w_hh[(16 + j) * 16 + k]);   // z row, half-scaled
        float wn = __ldg(&w_hh[(32 + j) * 16 + k]);          // n row
        wrz_[k] = pk2(wr, wz);
        wn_[k]  = pk2(wn, wn);
    }

    // --- tail constants ---
    float wirf = 0.5f * __ldg(&w_ih[j]);
    float wizf = 0.5f * __ldg(&w_ih[16 + j]);
    float winf = __ldg(&w_ih[32 + j]);
    float bsrf = 0.5f * (__ldg(&b_ih[j]) + __ldg(&b_hh[j]));
    float bszf = 0.5f * (__ldg(&b_ih[16 + j]) + __ldg(&b_hh[16 + j]));
    float binf = __ldg(&b_ih[32 + j]);
    float bhnf = __ldg(&b_hh[32 + j]);
    ull wirzp = pk2(wirf, wizf);    // x coefficient for gate-packed chains
    ull bRZ   = pk2(bsrf, bszf);    // chain init (complete bias, both gates)
    ull bN2   = pk2(bhnf, bhnf);
    ull winp  = pk2(winf, winf);
    ull bin2  = pk2(binf, binf);

    // ping-pong pointers (static offsets, swapped each step)
    ull* rd = &hbuf[0][grp * GSTRIDE];   // layouts: dup0 +0, dup1 +16, mix +32
    ull* wr = &hbuf[1][grp * GSTRIDE];

    ull hpk = 0ull;                 // packed (h0_j, h1_j)
    rd[j]      = 0ull;
    rd[16 + j] = 0ull;
    rd[32 + j] = 0ull;
    __syncwarp();

    const float2* xp = ((const float2*)g_xT) + p;
    float2 xv = __ldg(xp);
    xp += (BB / 2);

    for (int t = 0; t < TT; t++) {
        ull x2  = pk2(xv.x, xv.y);
        ull x0d = pk2(xv.x, xv.x);
        ull x1d = pk2(xv.y, xv.y);
        float2 xnext = __ldg(xp);      // padded array: always valid
        xp += (BB / 2);

        // chain inits: x-terms into r/z chains (complete bias preloaded)
        ull A1 = ffma2(x0d, wirzp, bRZ);   // (aR0, aZ0)
        ull A2 = ffma2(x1d, wirzp, bRZ);   // (aR1, aZ1)
        ull AN = bN2;                      // (aN0, aN1) = gh_n + b_hh_n

        // dot phase: 24 broadcast LDS.128, 48 ffma2, 3 independent chains
#pragma unroll
        for (int k2 = 0; k2 < 8; k2++) {
            ulonglong2 d0 = *(const ulonglong2*)(rd + 2 * k2);        // (h0,h0) x2
            ulonglong2 d1 = *(const ulonglong2*)(rd + 16 + 2 * k2);   // (h1,h1) x2
            ulonglong2 mm = *(const ulonglong2*)(rd + 32 + 2 * k2);   // (h0,h1) x2
            A1 = ffma2(wrz_[2 * k2], d0.x, A1);
            A2 = ffma2(wrz_[2 * k2], d1.x, A2);
            AN = ffma2(wn_[2 * k2],  mm.x, AN);
            A1 = ffma2(wrz_[2 * k2 + 1], d0.y, A1);
            A2 = ffma2(wrz_[2 * k2 + 1], d1.y, A2);
            AN = ffma2(wn_[2 * k2 + 1],  mm.y, AN);
        }

        // tail: no horizontal adds — pre-activations are complete
        float a0, b0, a1, b1;
        upk2(A1, a0, b0);
        upk2(A2, a1, b1);
        float r0 = fmaf(0.5f, tanh_mufu(a0), 0.5f);
        float z0 = fmaf(0.5f, tanh_mufu(b0), 0.5f);
        float r1 = fmaf(0.5f, tanh_mufu(a1), 0.5f);
        float z1 = fmaf(0.5f, tanh_mufu(b1), 0.5f);
        ull rr = pk2(r0, r1);
        ull zz = pk2(z0, z1);
        ull gi = ffma2(x2, winp, bin2);
        ull npre = ffma2(rr, AN, gi);
        float plo, phi;
        upk2(npre, plo, phi);
        ull nn = pk2(tanh_mufu(plo), tanh_mufu(phi));
        hpk = ffma2(zz, fsub2(hpk, nn), nn);     // h' = n + z*(h - n)

        // exchange: 3 layouts, one syncwarp
        float h0, h1;
        upk2(hpk, h0, h1);
        wr[j]      = pk2(h0, h0);
        wr[16 + j] = pk2(h1, h1);
        wr[32 + j] = hpk;
        __syncwarp();
        ull* tp = rd; rd = wr; wr = tp;

        xv = xnext;
    }

    // FC epilogue: out[b] = sum_j h[b][j] * w_fc[j] + b_fc
    float wf = __ldg(&w_fc[j]);
    float h0, h1;
    upk2(hpk, h0, h1);
    float s0 = h0 * wf;
    float s1 = h1 * wf;
#pragma unroll
    for (int d = 1; d < 16; d <<= 1) {
        s0 += __shfl_xor_sync(0xffffffffu, s0, d);
        s1 += __shfl_xor_sync(0xffffffffu, s1, d);
    }
    if (j == 0) {
        float bf = __ldg(b_fc);
        float2 o;
        o.x = s0 + bf;
        o.y = s1 + bf;
        *(float2*)(out + 2 * p) = o;
    }
}

// ---------------------------------------------------------------------------
extern "C" void kernel_launch(void* const* d_in, const int* in_sizes, int n_in,
                              void* d_out, int out_size)
{
    const float* x    = (const float*)d_in[0];
    const float* w_ih = (const float*)d_in[1];
    const float* w_hh = (const float*)d_in[2];
    const float* b_ih = (const float*)d_in[3];
    const float* b_hh = (const float*)d_in[4];
    const float* w_fc = (const float*)d_in[5];
    const float* b_fc = (const float*)d_in[6];
    float* out = (float*)d_out;

    dim3 tb(32, 8);
    dim3 tg(TT / 32, BB / 32);
    transpose_kernel<<<tg, tb>>>(x);

    // 16384 batch / 2 per 16-lane group * 16 lanes = 131072 threads
    // = 1024 blocks x 128 threads, 4 blocks/SM (spill-free, round-6 shape).
    gru_kernel<<<1024, 128>>>(w_ih, w_hh, b_ih, b_hh, w_fc, b_fc, out);
}